// round 3
// baseline (speedup 1.0000x reference)
#include <cuda_runtime.h>
#include <math.h>

#define B_    2
#define NB_   512
#define L_    64
#define H_    8
#define DH_   64
#define C_    512
#define C3_   1536
#define MROWS 65536          // B*NB*L
#define BNB   1024           // B*NB
#define NBLL  2097152        // NB*L*L

// ---------------- static scratch (no allocations allowed) ----------------
__device__ float g_qkv   [100663296];  // [MROWS][1536]
__device__ float g_xmid  [33554432];   // [MROWS][512]
__device__ float g_gate  [16777216];   // [H][NB][L][L]
__device__ float g_smask [2097152];    // [NB][L][L]   bias3 + (mask?0:-1e30)
__device__ float g_gblock[524288];     // [MROWS][H]
__device__ float g_vblock[524288];     // [BNB][512]
__device__ float g_bnode [524288];     // [BNB][512]

// ================= prep: fixed mask, bias diag, gate MLP =================
__global__ void prep_kernel(const int* __restrict__ mask,
                            const float* __restrict__ ef,
                            const float* __restrict__ w1, const float* __restrict__ b1,
                            const float* __restrict__ w2, const float* __restrict__ b2)
{
    __shared__ float sw1[64], sb1[16], sw2[128], sb2[8];
    __shared__ int ssum;
    int t   = threadIdx.x;          // k index, 0..63
    int nbq = blockIdx.x;           // nb*64+q
    int q   = nbq & 63;
    sw1[t] = w1[t];
    sw2[t] = w2[t]; sw2[t + 64] = w2[t + 64];
    if (t < 16) sb1[t] = b1[t];
    if (t < 8)  sb2[t] = b2[t];
    if (t == 0) ssum = 0;
    __syncthreads();
    int m = mask[nbq * 64 + t];
    atomicAdd(&ssum, m);
    __syncthreads();
    int mf = m;
    if (q == t && ssum == 0) mf = 1;    // diag forced when row fully masked

    float e0, e1, e2, e3;
    if (q == t) { e0 = e1 = e2 = 0.f; e3 = 1.f; }
    else {
        const float* p = ef + ((size_t)nbq * 64 + t) * 4;
        e0 = p[0]; e1 = p[1]; e2 = p[2]; e3 = p[3];
    }
    float hb[16];
    #pragma unroll
    for (int i = 0; i < 16; i++) {
        float s = sb1[i] + e0 * sw1[i] + e1 * sw1[16 + i] + e2 * sw1[32 + i] + e3 * sw1[48 + i];
        hb[i] = 0.5f * s * (1.f + erff(s * 0.70710678118654752f));
    }
    #pragma unroll
    for (int h = 0; h < 8; h++) {
        float s = sb2[h];
        #pragma unroll
        for (int i = 0; i < 16; i++) s += hb[i] * sw2[i * 8 + h];
        g_gate[h * NBLL + nbq * 64 + t] = mf ? s : 0.f;
    }
    g_smask[nbq * 64 + t] = e3 + (mf ? 0.f : -1e30f);
}

// ================= block mean =================
__global__ void bnode_kernel(const float* __restrict__ x)
{
    int bn = blockIdx.x, c = threadIdx.x;   // 512 threads
    const float* p = x + (size_t)bn * 64 * 512 + c;
    float s = 0.f;
    #pragma unroll 8
    for (int l = 0; l < 64; l++) s += p[l * 512];
    g_bnode[bn * 512 + c] = s * (1.f / 64.f);
}

// ================= v_block = bnode @ w_qkv[:,2C:] + b =================
__global__ void vblock_kernel(const float* __restrict__ wqkv, const float* __restrict__ bqkv)
{
    __shared__ float sA[16][512];
    int t = threadIdx.x;                 // 512
    int r0 = blockIdx.x * 16;
    for (int r = 0; r < 16; r++) sA[r][t] = g_bnode[(r0 + r) * 512 + t];
    __syncthreads();
    float acc[16];
    #pragma unroll
    for (int r = 0; r < 16; r++) acc[r] = 0.f;
    for (int k = 0; k < 512; k++) {
        float w = wqkv[(size_t)k * 1536 + 1024 + t];
        #pragma unroll
        for (int r = 0; r < 16; r++) acc[r] += sA[r][k] * w;
    }
    float bb = bqkv[1024 + t];
    #pragma unroll
    for (int r = 0; r < 16; r++) g_vblock[(r0 + r) * 512 + t] = acc[r] + bb;
}

// ================= g_block = sigmoid(x @ w_blk + b) =================
__global__ void gblock_kernel(const float* __restrict__ x,
                              const float* __restrict__ wblk, const float* __restrict__ bblk)
{
    int w = threadIdx.x >> 5, lane = threadIdx.x & 31;
    int row = blockIdx.x * 8 + w;
    float acc[8];
    #pragma unroll
    for (int h = 0; h < 8; h++) acc[h] = 0.f;
    #pragma unroll 4
    for (int i = 0; i < 16; i++) {
        int c = i * 32 + lane;
        float xv = x[(size_t)row * 512 + c];
        float4 w0 = *(const float4*)(wblk + c * 8);
        float4 w1 = *(const float4*)(wblk + c * 8 + 4);
        acc[0] += xv * w0.x; acc[1] += xv * w0.y; acc[2] += xv * w0.z; acc[3] += xv * w0.w;
        acc[4] += xv * w1.x; acc[5] += xv * w1.y; acc[6] += xv * w1.z; acc[7] += xv * w1.w;
    }
    #pragma unroll
    for (int m = 16; m; m >>= 1) {
        #pragma unroll
        for (int h = 0; h < 8; h++) acc[h] += __shfl_xor_sync(0xffffffffu, acc[h], m);
    }
    if (lane == 0) {
        #pragma unroll
        for (int h = 0; h < 8; h++)
            g_gblock[row * 8 + h] = 1.f / (1.f + __expf(-(acc[h] + bblk[h])));
    }
}

// ================= SGEMM: C = A[M,K] @ B[K,N] + bias =================
__global__ void __launch_bounds__(256) sgemm_bias_kernel(
    const float* __restrict__ A, const float* __restrict__ Bm,
    const float* __restrict__ bias, float* __restrict__ Cm, int N, int K)
{
    __shared__ __align__(16) float As[16][132];
    __shared__ __align__(16) float Bs[16][128];
    int tid = threadIdx.x;
    int tx = tid & 15, ty = tid >> 4;
    int row0 = blockIdx.y * 128, col0 = blockIdx.x * 128;
    float acc[8][8] = {};
    for (int k0 = 0; k0 < K; k0 += 16) {
        #pragma unroll
        for (int p = 0; p < 2; p++) {
            int fid = p * 256 + tid;
            int r = fid >> 2, c4 = (fid & 3) * 4;
            float4 a = *(const float4*)(A + (size_t)(row0 + r) * K + k0 + c4);
            As[c4 + 0][r] = a.x; As[c4 + 1][r] = a.y; As[c4 + 2][r] = a.z; As[c4 + 3][r] = a.w;
        }
        #pragma unroll
        for (int p = 0; p < 2; p++) {
            int fid = p * 256 + tid;
            int kk = fid >> 5, c4 = (fid & 31) * 4;
            *(float4*)(&Bs[kk][c4]) = *(const float4*)(Bm + (size_t)(k0 + kk) * N + col0 + c4);
        }
        __syncthreads();
        #pragma unroll
        for (int kk = 0; kk < 16; kk++) {
            float4 a0 = *(const float4*)(&As[kk][ty * 8]);
            float4 a1 = *(const float4*)(&As[kk][ty * 8 + 4]);
            float4 b0 = *(const float4*)(&Bs[kk][tx * 8]);
            float4 b1 = *(const float4*)(&Bs[kk][tx * 8 + 4]);
            float ar[8] = {a0.x, a0.y, a0.z, a0.w, a1.x, a1.y, a1.z, a1.w};
            float br[8] = {b0.x, b0.y, b0.z, b0.w, b1.x, b1.y, b1.z, b1.w};
            #pragma unroll
            for (int i = 0; i < 8; i++)
                #pragma unroll
                for (int j = 0; j < 8; j++)
                    acc[i][j] += ar[i] * br[j];
        }
        __syncthreads();
    }
    #pragma unroll
    for (int i = 0; i < 8; i++) {
        int row = row0 + ty * 8 + i;
        #pragma unroll
        for (int j4 = 0; j4 < 2; j4++) {
            int col = col0 + tx * 8 + j4 * 4;
            float4 bv = *(const float4*)(bias + col);
            float4 o;
            o.x = acc[i][j4 * 4 + 0] + bv.x;
            o.y = acc[i][j4 * 4 + 1] + bv.y;
            o.z = acc[i][j4 * 4 + 2] + bv.z;
            o.w = acc[i][j4 * 4 + 3] + bv.w;
            *(float4*)(Cm + (size_t)row * N + col) = o;
        }
    }
}

// ================= attention per (b,nb,h) =================
__device__ __forceinline__ int swz(int row, int col) {      // scalar swizzled [row][64]
    return row * 64 + ((((col >> 2) ^ (row & 15)) << 2) | (col & 3));
}
__device__ __forceinline__ int swz4(int row, int c4) {      // float4 base addr
    return row * 64 + (((c4) ^ (row & 15)) << 2);
}

__global__ void __launch_bounds__(256) attn_kernel()
{
    __shared__ __align__(16) float qT[64 * 64];   // swizzled transposed [d][l]; reused as ss[k][q]
    __shared__ __align__(16) float kT[64 * 64];   // swizzled transposed [d][l]
    __shared__ __align__(16) float vs[64 * 64];   // natural [l][d]
    int tid = threadIdx.x;
    int cid = blockIdx.x;
    int h  = cid & 7;
    int bn = cid >> 3;           // b*NB+nb
    int nb = bn & 511;
    int rbase = bn * 64;

    #pragma unroll
    for (int p = 0; p < 4; p++) {
        int fid = p * 256 + tid;
        int l = fid >> 4, d4 = (fid & 15) * 4;
        const float* base = g_qkv + (size_t)(rbase + l) * 1536 + h * 64 + d4;
        float4 qv = *(const float4*)(base);
        float4 kv = *(const float4*)(base + 512);
        float4 vv = *(const float4*)(base + 1024);
        qT[swz(d4 + 0, l)] = qv.x; qT[swz(d4 + 1, l)] = qv.y;
        qT[swz(d4 + 2, l)] = qv.z; qT[swz(d4 + 3, l)] = qv.w;
        kT[swz(d4 + 0, l)] = kv.x; kT[swz(d4 + 1, l)] = kv.y;
        kT[swz(d4 + 2, l)] = kv.z; kT[swz(d4 + 3, l)] = kv.w;
        *(float4*)(&vs[l * 64 + d4]) = vv;
    }
    __syncthreads();

    int tq = tid >> 4, tk = tid & 15;
    int qi0 = tq * 4, ki0 = tk * 4;

    // ---- scores = q k^T ----
    float acc[4][4] = {};
    #pragma unroll 8
    for (int d = 0; d < 64; d++) {
        float4 a = *(const float4*)(&qT[swz4(d, tq)]);
        float4 b = *(const float4*)(&kT[swz4(d, tk)]);
        float ar[4] = {a.x, a.y, a.z, a.w};
        float br[4] = {b.x, b.y, b.z, b.w};
        #pragma unroll
        for (int i = 0; i < 4; i++)
            #pragma unroll
            for (int j = 0; j < 4; j++)
                acc[i][j] += ar[i] * br[j];
    }

    // ---- mask+bias, softmax over k (16-lane half-warp rows), +gate ----
    const float* smp = g_smask + nb * 4096;
    #pragma unroll
    for (int i = 0; i < 4; i++) {
        int qrow = qi0 + i;
        float s[4];
        #pragma unroll
        for (int j = 0; j < 4; j++)
            s[j] = acc[i][j] * 0.125f + smp[qrow * 64 + ki0 + j];
        float mx = fmaxf(fmaxf(s[0], s[1]), fmaxf(s[2], s[3]));
        #pragma unroll
        for (int m = 8; m; m >>= 1) mx = fmaxf(mx, __shfl_xor_sync(0xffffffffu, mx, m, 16));
        float sum = 0.f;
        #pragma unroll
        for (int j = 0; j < 4; j++) { s[j] = __expf(s[j] - mx); sum += s[j]; }
        #pragma unroll
        for (int m = 8; m; m >>= 1) sum += __shfl_xor_sync(0xffffffffu, sum, m, 16);
        float inv = 1.f / sum;
        const float* gp = g_gate + h * NBLL + nb * 4096 + qrow * 64 + ki0;
        #pragma unroll
        for (int j = 0; j < 4; j++) acc[i][j] = s[j] * inv + gp[j];
    }
    __syncthreads();                        // everyone done reading qT
    float* ss = qT;                         // combined^T [k][q]
    #pragma unroll
    for (int i = 0; i < 4; i++)
        #pragma unroll
        for (int j = 0; j < 4; j++)
            ss[swz(ki0 + j, qi0 + i)] = acc[i][j];
    __syncthreads();

    // ---- out = combined @ v ----
    float o[4][4] = {};
    int dj0 = tk * 4;
    #pragma unroll 8
    for (int k = 0; k < 64; k++) {
        float4 a = *(const float4*)(&ss[swz4(k, tq)]);
        float4 b = *(const float4*)(&vs[k * 64 + dj0]);
        float ar[4] = {a.x, a.y, a.z, a.w};
        float br[4] = {b.x, b.y, b.z, b.w};
        #pragma unroll
        for (int i = 0; i < 4; i++)
            #pragma unroll
            for (int j = 0; j < 4; j++)
                o[i][j] += ar[i] * br[j];
    }

    // ---- + g_block * v_block, store ----
    float4 vb = *(const float4*)(g_vblock + bn * 512 + h * 64 + dj0);
    #pragma unroll
    for (int i = 0; i < 4; i++) {
        int row = rbase + qi0 + i;
        float gb = g_gblock[row * 8 + h];
        float4 outv;
        outv.x = o[i][0] + gb * vb.x;
        outv.y = o[i][1] + gb * vb.y;
        outv.z = o[i][2] + gb * vb.z;
        outv.w = o[i][3] + gb * vb.w;
        *(float4*)(g_xmid + (size_t)row * 512 + h * 64 + dj0) = outv;
    }
}

// ================= launch =================
extern "C" void kernel_launch(void* const* d_in, const int* in_sizes, int n_in,
                              void* d_out, int out_size)
{
    const float* x       = (const float*)d_in[0];
    const int*   amask   = (const int*)  d_in[1];
    const float* edge    = (const float*)d_in[2];
    const float* w_qkv   = (const float*)d_in[3];
    const float* b_qkv   = (const float*)d_in[4];
    const float* w_proj  = (const float*)d_in[5];
    const float* b_proj  = (const float*)d_in[6];
    const float* w_eg1   = (const float*)d_in[7];
    const float* b_eg1   = (const float*)d_in[8];
    const float* w_eg2   = (const float*)d_in[9];
    const float* b_eg2   = (const float*)d_in[10];
    const float* w_blk   = (const float*)d_in[11];
    const float* b_blk   = (const float*)d_in[12];
    float* out = (float*)d_out;

    void *qkvp = nullptr, *xmidp = nullptr;
    cudaGetSymbolAddress(&qkvp, g_qkv);
    cudaGetSymbolAddress(&xmidp, g_xmid);

    prep_kernel  <<<NB_ * 64, 64>>>(amask, edge, w_eg1, b_eg1, w_eg2, b_eg2);
    bnode_kernel <<<BNB, 512>>>(x);
    vblock_kernel<<<64, 512>>>(w_qkv, b_qkv);
    gblock_kernel<<<MROWS / 8, 256>>>(x, w_blk, b_blk);
    sgemm_bias_kernel<<<dim3(12, 512), 256>>>(x, w_qkv, b_qkv, (float*)qkvp, 1536, 512);
    attn_kernel  <<<BNB * H_, 256>>>();
    sgemm_bias_kernel<<<dim3(4, 512), 256>>>((const float*)xmidp, w_proj, b_proj, out, 512, 512);
}

// round 5
// speedup vs baseline: 2.0328x; 2.0328x over previous
#include <cuda_runtime.h>
#include <cuda_bf16.h>
#include <math.h>
#include <stdint.h>

#define B_    2
#define NB_   512
#define L_    64
#define H_    8
#define DH_   64
#define C_    512
#define C3_   1536
#define MROWS 65536          // B*NB*L
#define BNB   1024           // B*NB
#define NBLL  2097152        // NB*L*L

// ---------------- static scratch (no allocations allowed) ----------------
__device__ float g_qkv   [100663296];  // [MROWS][1536] fp32
__device__ float g_gate  [16777216];   // [H][NB][L][L]
__device__ float g_smask [2097152];    // [NB][L][L]   bias3 + (mask?0:-1e30)
__device__ float g_gblock[524288];     // [MROWS][H]
__device__ float g_vblock[524288];     // [BNB][512]
__device__ float g_bnode [524288];     // [BNB][512]
__device__ __nv_bfloat16 g_xh[33554432];   // x hi  [MROWS][512]
__device__ __nv_bfloat16 g_xl[33554432];   // x lo
__device__ __nv_bfloat16 g_mh[33554432];   // xmid hi
__device__ __nv_bfloat16 g_ml[33554432];   // xmid lo
__device__ __nv_bfloat16 g_wqh[786432];    // w_qkv^T hi [1536][512]
__device__ __nv_bfloat16 g_wql[786432];
__device__ __nv_bfloat16 g_wph[262144];    // w_proj^T hi [512][512]
__device__ __nv_bfloat16 g_wpl[262144];

// =================== PTX helpers (baseline ISA only: sm_80+) ===================
__device__ __forceinline__ uint32_t s2u(const void* p) {
    return (uint32_t)__cvta_generic_to_shared(p);
}
__device__ __forceinline__ void cp16(uint32_t dst, const void* src) {
    asm volatile("cp.async.cg.shared.global [%0], [%1], 16;" :: "r"(dst), "l"(src));
}
#define LDSM4(r, a) \
    asm volatile("ldmatrix.sync.aligned.m8n8.x4.shared.b16 {%0,%1,%2,%3}, [%4];" \
        : "=r"((r)[0]), "=r"((r)[1]), "=r"((r)[2]), "=r"((r)[3]) : "r"(a))
#define MMA16816(c, a, b) \
    asm volatile("mma.sync.aligned.m16n8k16.row.col.f32.bf16.bf16.f32 " \
        "{%0,%1,%2,%3}, {%4,%5,%6,%7}, {%8,%9}, {%0,%1,%2,%3};" \
        : "+f"((c)[0]), "+f"((c)[1]), "+f"((c)[2]), "+f"((c)[3]) \
        : "r"((a)[0]), "r"((a)[1]), "r"((a)[2]), "r"((a)[3]), "r"((b)[0]), "r"((b)[1]))

// =================== bf16x2-split GEMM via HMMA mma.sync ===================
// C[M,N] = A@W^T + bias, A split hi/lo [M][512] bf16 K-major,
// B = W^T split hi/lo [N][512] bf16 K-major.
// 3 passes: hi*hi + hi*lo + lo*hi into shared fp32 accumulators.
#define STAGE_BYTES 65536        // 4 tiles x 128x64 bf16 (Ah Al Bh Bl)
#define GSMEM (2 * STAGE_BYTES)  // double buffered

__device__ __forceinline__ void gemm_load_stage(
    uint32_t st, int tid, int kc,
    const __nv_bfloat16* __restrict__ A_h, const __nv_bfloat16* __restrict__ A_l,
    const __nv_bfloat16* __restrict__ B_h, const __nv_bfloat16* __restrict__ B_l)
{
    const __nv_bfloat16* bases[4] = {A_h, A_l, B_h, B_l};
    #pragma unroll
    for (int t = 0; t < 4; t++) {
        uint32_t dst = st + t * 16384;
        const __nv_bfloat16* bp = bases[t] + kc * 64;
        #pragma unroll
        for (int r = 0; r < 4; r++) {
            int idx = r * 256 + tid;          // 0..1023 = 128 rows x 8 chunks
            int row = idx >> 3, ch = idx & 7;
            cp16(dst + row * 128 + ((ch ^ (row & 7)) << 4),
                 bp + (size_t)row * 512 + ch * 8);
        }
    }
    asm volatile("cp.async.commit_group;" ::: "memory");
}

__global__ void __launch_bounds__(256)
gemm_bf16x2_kernel(const __nv_bfloat16* __restrict__ Ah, const __nv_bfloat16* __restrict__ Al,
                   const __nv_bfloat16* __restrict__ Bh, const __nv_bfloat16* __restrict__ Bl,
                   const float* __restrict__ bias, float* __restrict__ C, int ldC)
{
    extern __shared__ __align__(1024) char smem[];
    uint32_t sb = s2u(smem);
    int tid = threadIdx.x;
    int warp = tid >> 5, lane = tid & 31;
    int m0 = blockIdx.y * 128, n0 = blockIdx.x * 128;
    int wm = (warp & 3) * 32, wn = (warp >> 2) * 64;

    const __nv_bfloat16* pAh = Ah + (size_t)m0 * 512;
    const __nv_bfloat16* pAl = Al + (size_t)m0 * 512;
    const __nv_bfloat16* pBh = Bh + (size_t)n0 * 512;
    const __nv_bfloat16* pBl = Bl + (size_t)n0 * 512;

    float acc[2][8][4];
    #pragma unroll
    for (int i = 0; i < 2; i++)
        #pragma unroll
        for (int j = 0; j < 8; j++)
            #pragma unroll
            for (int t = 0; t < 4; t++) acc[i][j][t] = 0.f;

    // precomputed ldmatrix row/lane geometry
    int aRow[2], bRow[4];
    #pragma unroll
    for (int mi = 0; mi < 2; mi++) aRow[mi] = wm + mi * 16 + (lane & 15);
    #pragma unroll
    for (int nj = 0; nj < 4; nj++) bRow[nj] = wn + nj * 16 + (lane & 7) + ((lane >> 4) << 3);
    int aSel = lane >> 4;          // 0/1 -> +8 in k
    int bSel = (lane >> 3) & 1;    // 0/1 -> +8 in k

    gemm_load_stage(sb, tid, 0, pAh, pAl, pBh, pBl);

    for (int kc = 0; kc < 8; kc++) {
        if (kc + 1 < 8) {
            gemm_load_stage(sb + ((kc + 1) & 1) * STAGE_BYTES, tid, kc + 1,
                            pAh, pAl, pBh, pBl);
            asm volatile("cp.async.wait_group 1;" ::: "memory");
        } else {
            asm volatile("cp.async.wait_group 0;" ::: "memory");
        }
        __syncthreads();

        uint32_t stA_h = sb + (kc & 1) * STAGE_BYTES;
        uint32_t stA_l = stA_h + 16384;
        uint32_t stB_h = stA_h + 32768;
        uint32_t stB_l = stA_h + 49152;

        #pragma unroll
        for (int kk = 0; kk < 4; kk++) {
            uint32_t ah[2][4], al[2][4], bh[4][4], bl[4][4];
            #pragma unroll
            for (int mi = 0; mi < 2; mi++) {
                int ch = kk * 2 + aSel;
                uint32_t ad = aRow[mi] * 128 + ((ch ^ (aRow[mi] & 7)) << 4);
                LDSM4(ah[mi], stA_h + ad);
                LDSM4(al[mi], stA_l + ad);
            }
            #pragma unroll
            for (int nj = 0; nj < 4; nj++) {
                int ch = kk * 2 + bSel;
                uint32_t bd = bRow[nj] * 128 + ((ch ^ (bRow[nj] & 7)) << 4);
                LDSM4(bh[nj], stB_h + bd);
                LDSM4(bl[nj], stB_l + bd);
            }
            #pragma unroll
            for (int mi = 0; mi < 2; mi++)
                #pragma unroll
                for (int nj = 0; nj < 4; nj++) {
                    MMA16816(acc[mi][nj * 2 + 0], ah[mi], (bh[nj] + 0));
                    MMA16816(acc[mi][nj * 2 + 1], ah[mi], (bh[nj] + 2));
                    MMA16816(acc[mi][nj * 2 + 0], ah[mi], (bl[nj] + 0));
                    MMA16816(acc[mi][nj * 2 + 1], ah[mi], (bl[nj] + 2));
                    MMA16816(acc[mi][nj * 2 + 0], al[mi], (bh[nj] + 0));
                    MMA16816(acc[mi][nj * 2 + 1], al[mi], (bh[nj] + 2));
                }
        }
        __syncthreads();
    }

    // epilogue: +bias, fp32 store
    #pragma unroll
    for (int mi = 0; mi < 2; mi++) {
        int row = m0 + wm + mi * 16 + (lane >> 2);
        #pragma unroll
        for (int ni = 0; ni < 8; ni++) {
            int col = n0 + wn + ni * 8 + (lane & 3) * 2;
            float2 bv = *(const float2*)(bias + col);
            float2 o0, o1;
            o0.x = acc[mi][ni][0] + bv.x; o0.y = acc[mi][ni][1] + bv.y;
            o1.x = acc[mi][ni][2] + bv.x; o1.y = acc[mi][ni][3] + bv.y;
            *(float2*)(C + (size_t)row * ldC + col) = o0;
            *(float2*)(C + (size_t)(row + 8) * ldC + col) = o1;
        }
    }
}

// ============ convert x -> bf16 hi/lo, fused g_block sigmoid ============
__global__ void __launch_bounds__(256) convx_kernel(const float* __restrict__ x,
    const float* __restrict__ wblk, const float* __restrict__ bblk)
{
    __shared__ __align__(16) float swt[8][512];   // wblk transposed
    int tid = threadIdx.x;
    for (int idx = tid; idx < 4096; idx += 256)
        swt[idx & 7][idx >> 3] = wblk[idx];
    __syncthreads();
    int wid = tid >> 5, lane = tid & 31;
    int row = blockIdx.x * 8 + wid;
    const float* xr = x + (size_t)row * 512;
    float acc[8] = {};
    #pragma unroll
    for (int i = 0; i < 4; i++) {
        int c = i * 128 + lane * 4;
        float4 v = *(const float4*)(xr + c);
        float vv[4] = {v.x, v.y, v.z, v.w};
        __nv_bfloat16 hh[4]; __nv_bfloat16 ll[4];
        #pragma unroll
        for (int j = 0; j < 4; j++) {
            hh[j] = __float2bfloat16(vv[j]);
            ll[j] = __float2bfloat16(vv[j] - __bfloat162float(hh[j]));
        }
        __nv_bfloat162 p0; p0.x = hh[0]; p0.y = hh[1];
        __nv_bfloat162 p1; p1.x = hh[2]; p1.y = hh[3];
        __nv_bfloat162 q0; q0.x = ll[0]; q0.y = ll[1];
        __nv_bfloat162 q1; q1.x = ll[2]; q1.y = ll[3];
        size_t o = (size_t)row * 512 + c;
        *(__nv_bfloat162*)(g_xh + o) = p0; *(__nv_bfloat162*)(g_xh + o + 2) = p1;
        *(__nv_bfloat162*)(g_xl + o) = q0; *(__nv_bfloat162*)(g_xl + o + 2) = q1;
        #pragma unroll
        for (int h = 0; h < 8; h++) {
            float4 wv = *(const float4*)(&swt[h][c]);
            acc[h] += vv[0] * wv.x + vv[1] * wv.y + vv[2] * wv.z + vv[3] * wv.w;
        }
    }
    #pragma unroll
    for (int m = 16; m; m >>= 1)
        #pragma unroll
        for (int h = 0; h < 8; h++) acc[h] += __shfl_xor_sync(0xffffffffu, acc[h], m);
    if (lane == 0) {
        #pragma unroll
        for (int h = 0; h < 8; h++)
            g_gblock[row * 8 + h] = 1.f / (1.f + __expf(-(acc[h] + bblk[h])));
    }
}

// ============ weight transpose + bf16 split: W[K][N] -> T[N][K] ============
__global__ void wsplit_kernel(const float* __restrict__ W,
    __nv_bfloat16* __restrict__ Th, __nv_bfloat16* __restrict__ Tl, int Kd, int Nd)
{
    __shared__ float tile[32][33];
    int tx = threadIdx.x & 31, ty = threadIdx.x >> 5;
    int n0 = blockIdx.x * 32, k0 = blockIdx.y * 32;
    #pragma unroll
    for (int r = 0; r < 4; r++)
        tile[ty + r * 8][tx] = W[(size_t)(k0 + ty + r * 8) * Nd + n0 + tx];
    __syncthreads();
    #pragma unroll
    for (int r = 0; r < 4; r++) {
        int n = ty + r * 8;
        float v = tile[tx][n];
        __nv_bfloat16 h = __float2bfloat16(v);
        size_t o = (size_t)(n0 + n) * Kd + k0 + tx;
        Th[o] = h;
        Tl[o] = __float2bfloat16(v - __bfloat162float(h));
    }
}

// ================= prep: fixed mask, bias diag, gate MLP =================
__global__ void prep_kernel(const int* __restrict__ mask,
                            const float* __restrict__ ef,
                            const float* __restrict__ w1, const float* __restrict__ b1,
                            const float* __restrict__ w2, const float* __restrict__ b2)
{
    __shared__ float sw1[64], sb1[16], sw2[128], sb2[8];
    __shared__ int ssum;
    int t   = threadIdx.x;          // k index
    int nbq = blockIdx.x;           // nb*64+q
    int q   = nbq & 63;
    sw1[t] = w1[t];
    sw2[t] = w2[t]; sw2[t + 64] = w2[t + 64];
    if (t < 16) sb1[t] = b1[t];
    if (t < 8)  sb2[t] = b2[t];
    if (t == 0) ssum = 0;
    __syncthreads();
    int m = mask[nbq * 64 + t];
    atomicAdd(&ssum, m);
    __syncthreads();
    int mf = m;
    if (q == t && ssum == 0) mf = 1;

    float e0, e1, e2, e3;
    if (q == t) { e0 = e1 = e2 = 0.f; e3 = 1.f; }
    else {
        const float* p = ef + ((size_t)nbq * 64 + t) * 4;
        e0 = p[0]; e1 = p[1]; e2 = p[2]; e3 = p[3];
    }
    float hb[16];
    #pragma unroll
    for (int i = 0; i < 16; i++) {
        float s = sb1[i] + e0 * sw1[i] + e1 * sw1[16 + i] + e2 * sw1[32 + i] + e3 * sw1[48 + i];
        hb[i] = 0.5f * s * (1.f + erff(s * 0.70710678118654752f));
    }
    #pragma unroll
    for (int h = 0; h < 8; h++) {
        float s = sb2[h];
        #pragma unroll
        for (int i = 0; i < 16; i++) s += hb[i] * sw2[i * 8 + h];
        g_gate[h * NBLL + nbq * 64 + t] = mf ? s : 0.f;
    }
    g_smask[nbq * 64 + t] = e3 + (mf ? 0.f : -1e30f);
}

// ================= block mean =================
__global__ void bnode_kernel(const float* __restrict__ x)
{
    int bn = blockIdx.x, c = threadIdx.x;   // 512 threads
    const float* p = x + (size_t)bn * 64 * 512 + c;
    float s = 0.f;
    #pragma unroll 8
    for (int l = 0; l < 64; l++) s += p[l * 512];
    g_bnode[bn * 512 + c] = s * (1.f / 64.f);
}

// ================= v_block = bnode @ w_qkv[:,2C:] + b =================
__global__ void vblock_kernel(const float* __restrict__ wqkv, const float* __restrict__ bqkv)
{
    __shared__ float sA[16][512];
    int t = threadIdx.x;                 // 512
    int r0 = blockIdx.x * 16;
    for (int r = 0; r < 16; r++) sA[r][t] = g_bnode[(r0 + r) * 512 + t];
    __syncthreads();
    float acc[16];
    #pragma unroll
    for (int r = 0; r < 16; r++) acc[r] = 0.f;
    for (int k = 0; k < 512; k++) {
        float w = wqkv[(size_t)k * 1536 + 1024 + t];
        #pragma unroll
        for (int r = 0; r < 16; r++) acc[r] += sA[r][k] * w;
    }
    float bb = bqkv[1024 + t];
    #pragma unroll
    for (int r = 0; r < 16; r++) g_vblock[(r0 + r) * 512 + t] = acc[r] + bb;
}

// ================= attention per (b,nb,h) =================
__device__ __forceinline__ int swz(int row, int col) {
    return row * 64 + ((((col >> 2) ^ (row & 15)) << 2) | (col & 3));
}
__device__ __forceinline__ int swz4(int row, int c4) {
    return row * 64 + (((c4) ^ (row & 15)) << 2);
}

__global__ void __launch_bounds__(256) attn_kernel()
{
    __shared__ __align__(16) float qT[64 * 64];
    __shared__ __align__(16) float kT[64 * 64];
    __shared__ __align__(16) float vs[64 * 64];
    int tid = threadIdx.x;
    int cid = blockIdx.x;
    int h  = cid & 7;
    int bn = cid >> 3;
    int nb = bn & 511;
    int rbase = bn * 64;

    #pragma unroll
    for (int p = 0; p < 4; p++) {
        int fid = p * 256 + tid;
        int l = fid >> 4, d4 = (fid & 15) * 4;
        const float* base = g_qkv + (size_t)(rbase + l) * 1536 + h * 64 + d4;
        float4 qv = *(const float4*)(base);
        float4 kv = *(const float4*)(base + 512);
        float4 vv = *(const float4*)(base + 1024);
        qT[swz(d4 + 0, l)] = qv.x; qT[swz(d4 + 1, l)] = qv.y;
        qT[swz(d4 + 2, l)] = qv.z; qT[swz(d4 + 3, l)] = qv.w;
        kT[swz(d4 + 0, l)] = kv.x; kT[swz(d4 + 1, l)] = kv.y;
        kT[swz(d4 + 2, l)] = kv.z; kT[swz(d4 + 3, l)] = kv.w;
        *(float4*)(&vs[l * 64 + d4]) = vv;
    }
    __syncthreads();

    int tq = tid >> 4, tk = tid & 15;
    int qi0 = tq * 4, ki0 = tk * 4;

    float acc[4][4] = {};
    #pragma unroll 8
    for (int d = 0; d < 64; d++) {
        float4 a = *(const float4*)(&qT[swz4(d, tq)]);
        float4 b = *(const float4*)(&kT[swz4(d, tk)]);
        float ar[4] = {a.x, a.y, a.z, a.w};
        float br[4] = {b.x, b.y, b.z, b.w};
        #pragma unroll
        for (int i = 0; i < 4; i++)
            #pragma unroll
            for (int j = 0; j < 4; j++)
                acc[i][j] += ar[i] * br[j];
    }

    const float* smp = g_smask + nb * 4096;
    #pragma unroll
    for (int i = 0; i < 4; i++) {
        int qrow = qi0 + i;
        float s[4];
        #pragma unroll
        for (int j = 0; j < 4; j++)
            s[j] = acc[i][j] * 0.125f + smp[qrow * 64 + ki0 + j];
        float mx = fmaxf(fmaxf(s[0], s[1]), fmaxf(s[2], s[3]));
        #pragma unroll
        for (int m = 8; m; m >>= 1) mx = fmaxf(mx, __shfl_xor_sync(0xffffffffu, mx, m, 16));
        float sum = 0.f;
        #pragma unroll
        for (int j = 0; j < 4; j++) { s[j] = __expf(s[j] - mx); sum += s[j]; }
        #pragma unroll
        for (int m = 8; m; m >>= 1) sum += __shfl_xor_sync(0xffffffffu, sum, m, 16);
        float inv = 1.f / sum;
        const float* gp = g_gate + h * NBLL + nb * 4096 + qrow * 64 + ki0;
        #pragma unroll
        for (int j = 0; j < 4; j++) acc[i][j] = s[j] * inv + gp[j];
    }
    __syncthreads();
    float* ss = qT;
    #pragma unroll
    for (int i = 0; i < 4; i++)
        #pragma unroll
        for (int j = 0; j < 4; j++)
            ss[swz(ki0 + j, qi0 + i)] = acc[i][j];
    __syncthreads();

    float o[4][4] = {};
    int dj0 = tk * 4;
    #pragma unroll 8
    for (int k = 0; k < 64; k++) {
        float4 a = *(const float4*)(&ss[swz4(k, tq)]);
        float4 b = *(const float4*)(&vs[k * 64 + dj0]);
        float ar[4] = {a.x, a.y, a.z, a.w};
        float br[4] = {b.x, b.y, b.z, b.w};
        #pragma unroll
        for (int i = 0; i < 4; i++)
            #pragma unroll
            for (int j = 0; j < 4; j++)
                o[i][j] += ar[i] * br[j];
    }

    float4 vb = *(const float4*)(g_vblock + bn * 512 + h * 64 + dj0);
    #pragma unroll
    for (int i = 0; i < 4; i++) {
        int row = rbase + qi0 + i;
        float gb = g_gblock[row * 8 + h];
        float ov[4];
        ov[0] = o[i][0] + gb * vb.x;
        ov[1] = o[i][1] + gb * vb.y;
        ov[2] = o[i][2] + gb * vb.z;
        ov[3] = o[i][3] + gb * vb.w;
        __nv_bfloat16 hh[4]; __nv_bfloat16 ll[4];
        #pragma unroll
        for (int j = 0; j < 4; j++) {
            hh[j] = __float2bfloat16(ov[j]);
            ll[j] = __float2bfloat16(ov[j] - __bfloat162float(hh[j]));
        }
        __nv_bfloat162 p0; p0.x = hh[0]; p0.y = hh[1];
        __nv_bfloat162 p1; p1.x = hh[2]; p1.y = hh[3];
        __nv_bfloat162 q0; q0.x = ll[0]; q0.y = ll[1];
        __nv_bfloat162 q1; q1.x = ll[2]; q1.y = ll[3];
        size_t ofs = (size_t)row * 512 + h * 64 + dj0;
        *(__nv_bfloat162*)(g_mh + ofs) = p0; *(__nv_bfloat162*)(g_mh + ofs + 2) = p1;
        *(__nv_bfloat162*)(g_ml + ofs) = q0; *(__nv_bfloat162*)(g_ml + ofs + 2) = q1;
    }
}

// ================= launch =================
extern "C" void kernel_launch(void* const* d_in, const int* in_sizes, int n_in,
                              void* d_out, int out_size)
{
    const float* x       = (const float*)d_in[0];
    const int*   amask   = (const int*)  d_in[1];
    const float* edge    = (const float*)d_in[2];
    const float* w_qkv   = (const float*)d_in[3];
    const float* b_qkv   = (const float*)d_in[4];
    const float* w_proj  = (const float*)d_in[5];
    const float* b_proj  = (const float*)d_in[6];
    const float* w_eg1   = (const float*)d_in[7];
    const float* b_eg1   = (const float*)d_in[8];
    const float* w_eg2   = (const float*)d_in[9];
    const float* b_eg2   = (const float*)d_in[10];
    const float* w_blk   = (const float*)d_in[11];
    const float* b_blk   = (const float*)d_in[12];
    float* out = (float*)d_out;

    void *qkvp, *xh, *xl, *mh, *ml, *wqh, *wql, *wph, *wpl;
    cudaGetSymbolAddress(&qkvp, g_qkv);
    cudaGetSymbolAddress(&xh, g_xh);   cudaGetSymbolAddress(&xl, g_xl);
    cudaGetSymbolAddress(&mh, g_mh);   cudaGetSymbolAddress(&ml, g_ml);
    cudaGetSymbolAddress(&wqh, g_wqh); cudaGetSymbolAddress(&wql, g_wql);
    cudaGetSymbolAddress(&wph, g_wph); cudaGetSymbolAddress(&wpl, g_wpl);

    cudaFuncSetAttribute(gemm_bf16x2_kernel,
                         cudaFuncAttributeMaxDynamicSharedMemorySize, GSMEM);

    convx_kernel<<<MROWS / 8, 256>>>(x, w_blk, b_blk);
    wsplit_kernel<<<dim3(48, 16), 256>>>(w_qkv, (__nv_bfloat16*)wqh, (__nv_bfloat16*)wql, 512, 1536);
    wsplit_kernel<<<dim3(16, 16), 256>>>(w_proj, (__nv_bfloat16*)wph, (__nv_bfloat16*)wpl, 512, 512);
    prep_kernel  <<<NB_ * 64, 64>>>(amask, edge, w_eg1, b_eg1, w_eg2, b_eg2);
    bnode_kernel <<<BNB, 512>>>(x);
    vblock_kernel<<<64, 512>>>(w_qkv, b_qkv);

    gemm_bf16x2_kernel<<<dim3(12, 512), 256, GSMEM>>>(
        (const __nv_bfloat16*)xh, (const __nv_bfloat16*)xl,
        (const __nv_bfloat16*)wqh, (const __nv_bfloat16*)wql,
        b_qkv, (float*)qkvp, 1536);

    attn_kernel<<<BNB * H_, 256>>>();

    gemm_bf16x2_kernel<<<dim3(4, 512), 256, GSMEM>>>(
        (const __nv_bfloat16*)mh, (const __nv_bfloat16*)ml,
        (const __nv_bfloat16*)wph, (const __nv_bfloat16*)wpl,
        b_proj, out, 512);
}